// round 1
// baseline (speedup 1.0000x reference)
#include <cuda_runtime.h>
#include <cuda_bf16.h>

#define NN 50000
#define NE 800000

// ---------------- device scratch (no allocations allowed) ----------------
__device__ float g_agg_h[NN * 64];   // scatter-sum of edge features
__device__ float g_sum_t[NN * 3];    // scatter-sum of clamped trans
__device__ float g_cnt[NN];          // out-degree (as float)

// vector reduction to global (sm_90+): 4 floats, 16B-aligned address
__device__ __forceinline__ void red_add_v4(float* p, float a, float b, float c, float d) {
    asm volatile("red.global.add.v4.f32 [%0], {%1,%2,%3,%4};"
                 :: "l"(p), "f"(a), "f"(b), "f"(c), "f"(d) : "memory");
}

// ---------------- zero scratch ----------------
__global__ void zero_kernel() {
    const int total = NN * 64 + NN * 3 + NN;
    for (int i = blockIdx.x * blockDim.x + threadIdx.x; i < total; i += gridDim.x * blockDim.x) {
        if (i < NN * 64)              g_agg_h[i] = 0.f;
        else if (i < NN * 64 + NN * 3) g_sum_t[i - NN * 64] = 0.f;
        else                           g_cnt[i - NN * 64 - NN * 3] = 0.f;
    }
}

// ---------------- edge kernel ----------------
// smem layout (floats):
//   sWe1 [129*64]=8256 @0, sbe1 [64] @8256, sWe2 [4096] @8320, sbe2 [64] @12416,
//   sWc1 [4096] @12480, sbc1 [64] @16576, sWc2 [64] @16640   -> 16704 floats = 66816 B
__global__ __launch_bounds__(128, 2)
void edge_kernel(const float* __restrict__ h, const float* __restrict__ coord,
                 const int* __restrict__ ei,
                 const float* __restrict__ We1, const float* __restrict__ be1,
                 const float* __restrict__ We2, const float* __restrict__ be2,
                 const float* __restrict__ Wc1, const float* __restrict__ bc1,
                 const float* __restrict__ Wc2, const float* __restrict__ bc2)
{
    extern __shared__ float s[];
    float* sWe1 = s;
    float* sbe1 = s + 8256;
    float* sWe2 = s + 8320;
    float* sbe2 = s + 12416;
    float* sWc1 = s + 12480;
    float* sbc1 = s + 16576;
    float* sWc2 = s + 16640;

    const int tid = threadIdx.x;
    for (int i = tid; i < 8256; i += 128) sWe1[i] = We1[i];
    for (int i = tid; i < 4096; i += 128) { sWe2[i] = We2[i]; sWc1[i] = Wc1[i]; }
    if (tid < 64) { sbe1[tid] = be1[tid]; sbe2[tid] = be2[tid]; sbc1[tid] = bc1[tid]; sWc2[tid] = Wc2[tid]; }
    __syncthreads();

    const int e = blockIdx.x * 128 + tid;
    if (e >= NE) return;
    const int r = ei[e];
    const int c = ei[NE + e];

    const float cdx = coord[r * 3 + 0] - coord[c * 3 + 0];
    const float cdy = coord[r * 3 + 1] - coord[c * 3 + 1];
    const float cdz = coord[r * 3 + 2] - coord[c * 3 + 2];
    const float radial = cdx * cdx + cdy * cdy + cdz * cdz;

    // ---- layer 1: acc = be1 + [h_r, h_c, radial] @ We1 ----
    float acc[64];
    #pragma unroll
    for (int j = 0; j < 64; j++) acc[j] = sbe1[j];

    const float4* hr4 = reinterpret_cast<const float4*>(h + (long)r * 64);
    const float4* hc4 = reinterpret_cast<const float4*>(h + (long)c * 64);

    #pragma unroll
    for (int half = 0; half < 2; half++) {
        const float4* src   = half ? hc4 : hr4;
        const float*  wbase = sWe1 + half * 64 * 64;
        for (int k4 = 0; k4 < 16; k4++) {
            const float4 x = src[k4];
            const float4* w0 = (const float4*)(wbase + (k4 * 4 + 0) * 64);
            const float4* w1 = (const float4*)(wbase + (k4 * 4 + 1) * 64);
            const float4* w2 = (const float4*)(wbase + (k4 * 4 + 2) * 64);
            const float4* w3 = (const float4*)(wbase + (k4 * 4 + 3) * 64);
            #pragma unroll
            for (int j = 0; j < 16; j++) {
                const float4 a0 = w0[j], a1 = w1[j], a2 = w2[j], a3 = w3[j];
                acc[4*j+0] += x.x*a0.x + x.y*a1.x + x.z*a2.x + x.w*a3.x;
                acc[4*j+1] += x.x*a0.y + x.y*a1.y + x.z*a2.y + x.w*a3.y;
                acc[4*j+2] += x.x*a0.z + x.y*a1.z + x.z*a2.z + x.w*a3.z;
                acc[4*j+3] += x.x*a0.w + x.y*a1.w + x.z*a2.w + x.w*a3.w;
            }
        }
    }
    {   // radial row (k = 128)
        const float4* w = (const float4*)(sWe1 + 128 * 64);
        #pragma unroll
        for (int j = 0; j < 16; j++) {
            const float4 a = w[j];
            acc[4*j+0] += radial * a.x; acc[4*j+1] += radial * a.y;
            acc[4*j+2] += radial * a.z; acc[4*j+3] += radial * a.w;
        }
    }

    // ---- layer 2: ef = relu(be2 + relu(acc) @ We2) ----
    float ef[64];
    #pragma unroll
    for (int j = 0; j < 64; j++) ef[j] = sbe2[j];
    for (int k = 0; k < 64; k++) {
        const float x = fmaxf(acc[k], 0.f);
        const float4* w = (const float4*)(sWe2 + k * 64);
        #pragma unroll
        for (int j = 0; j < 16; j++) {
            const float4 a = w[j];
            ef[4*j+0] += x*a.x; ef[4*j+1] += x*a.y; ef[4*j+2] += x*a.z; ef[4*j+3] += x*a.w;
        }
    }
    #pragma unroll
    for (int j = 0; j < 64; j++) ef[j] = fmaxf(ef[j], 0.f);

    // ---- gate: relu(ef @ Wc1 + bc1) @ Wc2 + bc2  (reuse acc as hidden) ----
    #pragma unroll
    for (int j = 0; j < 64; j++) acc[j] = sbc1[j];
    for (int k = 0; k < 64; k++) {
        const float x = ef[k];
        const float4* w = (const float4*)(sWc1 + k * 64);
        #pragma unroll
        for (int j = 0; j < 16; j++) {
            const float4 a = w[j];
            acc[4*j+0] += x*a.x; acc[4*j+1] += x*a.y; acc[4*j+2] += x*a.z; acc[4*j+3] += x*a.w;
        }
    }
    float gate = bc2[0];
    #pragma unroll
    for (int j = 0; j < 64; j++) gate += fmaxf(acc[j], 0.f) * sWc2[j];

    const float tx = fminf(fmaxf(cdx * gate, -100.f), 100.f);
    const float ty = fminf(fmaxf(cdy * gate, -100.f), 100.f);
    const float tz = fminf(fmaxf(cdz * gate, -100.f), 100.f);

    atomicAdd(&g_sum_t[r * 3 + 0], tx);
    atomicAdd(&g_sum_t[r * 3 + 1], ty);
    atomicAdd(&g_sum_t[r * 3 + 2], tz);
    atomicAdd(&g_cnt[r], 1.0f);

    float* dst = g_agg_h + (long)r * 64;
    #pragma unroll
    for (int j = 0; j < 16; j++)
        red_add_v4(dst + 4 * j, ef[4*j+0], ef[4*j+1], ef[4*j+2], ef[4*j+3]);
}

// ---------------- node kernel ----------------
// smem: sWn1 [128*64]=8192 @0, sbn1 [64] @8192, sWn2 [4096] @8256, sbn2 [64] @12352
//   -> 12416 floats = 49664 B
__global__ __launch_bounds__(128, 2)
void node_kernel(const float* __restrict__ h, const float* __restrict__ coord,
                 const float* __restrict__ vel,
                 const float* __restrict__ Wn1, const float* __restrict__ bn1,
                 const float* __restrict__ Wn2, const float* __restrict__ bn2,
                 float* __restrict__ out)
{
    extern __shared__ float s[];
    float* sWn1 = s;
    float* sbn1 = s + 8192;
    float* sWn2 = s + 8256;
    float* sbn2 = s + 12352;

    const int tid = threadIdx.x;
    for (int i = tid; i < 8192; i += 128) sWn1[i] = Wn1[i];
    for (int i = tid; i < 4096; i += 128) sWn2[i] = Wn2[i];
    if (tid < 64) { sbn1[tid] = bn1[tid]; sbn2[tid] = bn2[tid]; }
    __syncthreads();

    const int n = blockIdx.x * 128 + tid;
    if (n >= NN) return;

    float acc[64];
    #pragma unroll
    for (int j = 0; j < 64; j++) acc[j] = sbn1[j];

    const float4* hn = reinterpret_cast<const float4*>(h + (long)n * 64);
    const float4* an = reinterpret_cast<const float4*>(g_agg_h + (long)n * 64);

    #pragma unroll
    for (int half = 0; half < 2; half++) {
        const float4* src   = half ? an : hn;
        const float*  wbase = sWn1 + half * 64 * 64;
        for (int k4 = 0; k4 < 16; k4++) {
            const float4 x = src[k4];
            const float4* w0 = (const float4*)(wbase + (k4 * 4 + 0) * 64);
            const float4* w1 = (const float4*)(wbase + (k4 * 4 + 1) * 64);
            const float4* w2 = (const float4*)(wbase + (k4 * 4 + 2) * 64);
            const float4* w3 = (const float4*)(wbase + (k4 * 4 + 3) * 64);
            #pragma unroll
            for (int j = 0; j < 16; j++) {
                const float4 a0 = w0[j], a1 = w1[j], a2 = w2[j], a3 = w3[j];
                acc[4*j+0] += x.x*a0.x + x.y*a1.x + x.z*a2.x + x.w*a3.x;
                acc[4*j+1] += x.x*a0.y + x.y*a1.y + x.z*a2.y + x.w*a3.y;
                acc[4*j+2] += x.x*a0.z + x.y*a1.z + x.z*a2.z + x.w*a3.z;
                acc[4*j+3] += x.x*a0.w + x.y*a1.w + x.z*a2.w + x.w*a3.w;
            }
        }
    }

    float o[64];
    #pragma unroll
    for (int j = 0; j < 64; j++) o[j] = sbn2[j];
    for (int k = 0; k < 64; k++) {
        const float x = fmaxf(acc[k], 0.f);
        const float4* w = (const float4*)(sWn2 + k * 64);
        #pragma unroll
        for (int j = 0; j < 16; j++) {
            const float4 a = w[j];
            o[4*j+0] += x*a.x; o[4*j+1] += x*a.y; o[4*j+2] += x*a.z; o[4*j+3] += x*a.w;
        }
    }

    // h_out = h + node_mlp(...)
    float4* outh = reinterpret_cast<float4*>(out + (long)n * 64);
    #pragma unroll
    for (int j = 0; j < 16; j++) {
        const float4 hv = hn[j];
        float4 ov;
        ov.x = hv.x + o[4*j+0]; ov.y = hv.y + o[4*j+1];
        ov.z = hv.z + o[4*j+2]; ov.w = hv.w + o[4*j+3];
        outh[j] = ov;
    }

    // coordinate / velocity update
    const float cnt = g_cnt[n];
    const float inv = cnt > 0.f ? 1.f / cnt : 0.f;
    const float ax = g_sum_t[n * 3 + 0] * inv;
    const float ay = g_sum_t[n * 3 + 1] * inv;
    const float az = g_sum_t[n * 3 + 2] * inv;
    const float invL = 0.125f;   // 1/N_LAYERS
    const float vx = vel[n * 3 + 0] + ax * invL;
    const float vy = vel[n * 3 + 1] + ay * invL;
    const float vz = vel[n * 3 + 2] + az * invL;
    const float cx = coord[n * 3 + 0] + vx * invL;
    const float cy = coord[n * 3 + 1] + vy * invL;
    const float cz = coord[n * 3 + 2] + vz * invL;

    float* outc = out + (long)NN * 64;
    float* outv = outc + (long)NN * 3;
    outc[n * 3 + 0] = cx; outc[n * 3 + 1] = cy; outc[n * 3 + 2] = cz;
    outv[n * 3 + 0] = vx; outv[n * 3 + 1] = vy; outv[n * 3 + 2] = vz;
}

// ---------------- launch ----------------
extern "C" void kernel_launch(void* const* d_in, const int* in_sizes, int n_in,
                              void* d_out, int out_size) {
    const float* h     = (const float*)d_in[0];
    const float* coord = (const float*)d_in[1];
    const float* vel   = (const float*)d_in[2];
    /* d_in[3] = vel_init (unused by reference) */
    const int*   ei    = (const int*)d_in[4];
    const float* We1 = (const float*)d_in[5];
    const float* be1 = (const float*)d_in[6];
    const float* We2 = (const float*)d_in[7];
    const float* be2 = (const float*)d_in[8];
    const float* Wn1 = (const float*)d_in[9];
    const float* bn1 = (const float*)d_in[10];
    const float* Wn2 = (const float*)d_in[11];
    const float* bn2 = (const float*)d_in[12];
    const float* Wc1 = (const float*)d_in[13];
    const float* bc1 = (const float*)d_in[14];
    const float* Wc2 = (const float*)d_in[15];
    const float* bc2 = (const float*)d_in[16];
    float* out = (float*)d_out;

    cudaFuncSetAttribute(edge_kernel, cudaFuncAttributeMaxDynamicSharedMemorySize, 66816);
    cudaFuncSetAttribute(node_kernel, cudaFuncAttributeMaxDynamicSharedMemorySize, 49664);

    zero_kernel<<<296, 256>>>();
    edge_kernel<<<NE / 128, 128, 66816>>>(h, coord, ei,
                                          We1, be1, We2, be2, Wc1, bc1, Wc2, bc2);
    node_kernel<<<(NN + 127) / 128, 128, 49664>>>(h, coord, vel,
                                                  Wn1, bn1, Wn2, bn2, out);
}

// round 2
// speedup vs baseline: 1.0092x; 1.0092x over previous
#include <cuda_runtime.h>
#include <cuda_bf16.h>

#define NN 50000
#define NE 800000

typedef unsigned long long ull;

// ---------------- device scratch (no allocations allowed) ----------------
__device__ float g_agg_h[NN * 64];   // scatter-sum of edge features
__device__ float g_sum_t[NN * 3];    // scatter-sum of clamped trans
__device__ float g_cnt[NN];          // out-degree (as float)

// vector reduction to global (sm_90+): 4 floats, 16B-aligned address
__device__ __forceinline__ void red_add_v4(float* p, float a, float b, float c, float d) {
    asm volatile("red.global.add.v4.f32 [%0], {%1,%2,%3,%4};"
                 :: "l"(p), "f"(a), "f"(b), "f"(c), "f"(d) : "memory");
}

// ---------------- packed f32x2 helpers (Blackwell) ----------------
__device__ __forceinline__ ull pack2(float a, float b) {
    ull r; asm("mov.b64 %0, {%1,%2};" : "=l"(r) : "f"(a), "f"(b)); return r;
}
__device__ __forceinline__ ull ffma2(ull a, ull b, ull c) {
    ull d; asm("fma.rn.f32x2 %0, %1, %2, %3;" : "=l"(d) : "l"(a), "l"(b), "l"(c)); return d;
}
__device__ __forceinline__ float2 unpack2(ull v) {
    float2 r; asm("mov.b64 {%0,%1}, %2;" : "=f"(r.x), "=f"(r.y) : "l"(v)); return r;
}

// ---------------- zero scratch ----------------
__global__ void zero_kernel() {
    const int total = NN * 64 + NN * 3 + NN;
    for (int i = blockIdx.x * blockDim.x + threadIdx.x; i < total; i += gridDim.x * blockDim.x) {
        if (i < NN * 64)              g_agg_h[i] = 0.f;
        else if (i < NN * 64 + NN * 3) g_sum_t[i - NN * 64] = 0.f;
        else                           g_cnt[i - NN * 64 - NN * 3] = 0.f;
    }
}

// packed GEMV step: acc[0..31] += xx * Wrow[k] (64 wide), weights in smem
__device__ __forceinline__ void gemv_row(ull* acc, ull xx, const float* wrow) {
    const ulonglong2* w = reinterpret_cast<const ulonglong2*>(wrow);
    #pragma unroll
    for (int j = 0; j < 16; j++) {
        ulonglong2 wv = w[j];
        acc[2*j]   = ffma2(xx, wv.x, acc[2*j]);
        acc[2*j+1] = ffma2(xx, wv.y, acc[2*j+1]);
    }
}

// ---------------- edge kernel ----------------
// smem layout (floats):
//   sWe1 [129*64]=8256 @0, sbe1 [64] @8256, sWe2 [4096] @8320, sbe2 [64] @12416,
//   sWc1 [4096] @12480, sbc1 [64] @16576, sWc2 [64] @16640   -> 16704 floats = 66816 B
__global__ __launch_bounds__(128, 2)
void edge_kernel(const float* __restrict__ h, const float* __restrict__ coord,
                 const int* __restrict__ ei,
                 const float* __restrict__ We1, const float* __restrict__ be1,
                 const float* __restrict__ We2, const float* __restrict__ be2,
                 const float* __restrict__ Wc1, const float* __restrict__ bc1,
                 const float* __restrict__ Wc2, const float* __restrict__ bc2)
{
    extern __shared__ float s[];
    float* sWe1 = s;
    float* sbe1 = s + 8256;
    float* sWe2 = s + 8320;
    float* sbe2 = s + 12416;
    float* sWc1 = s + 12480;
    float* sbc1 = s + 16576;
    float* sWc2 = s + 16640;

    const int tid = threadIdx.x;
    for (int i = tid; i < 8256; i += 128) sWe1[i] = We1[i];
    for (int i = tid; i < 4096; i += 128) { sWe2[i] = We2[i]; sWc1[i] = Wc1[i]; }
    if (tid < 64) { sbe1[tid] = be1[tid]; sbe2[tid] = be2[tid]; sbc1[tid] = bc1[tid]; sWc2[tid] = Wc2[tid]; }
    __syncthreads();

    const int e = blockIdx.x * 128 + tid;
    if (e >= NE) return;
    const int r = ei[e];
    const int c = ei[NE + e];

    const float cdx = coord[r * 3 + 0] - coord[c * 3 + 0];
    const float cdy = coord[r * 3 + 1] - coord[c * 3 + 1];
    const float cdz = coord[r * 3 + 2] - coord[c * 3 + 2];
    const float radial = cdx * cdx + cdy * cdy + cdz * cdz;

    // ---- layer 1: acc = be1 + [h_r, h_c, radial] @ We1 ----
    ull acc[32];
    {
        const ulonglong2* b = reinterpret_cast<const ulonglong2*>(sbe1);
        #pragma unroll
        for (int j = 0; j < 16; j++) { ulonglong2 t = b[j]; acc[2*j] = t.x; acc[2*j+1] = t.y; }
    }

    const float4* hr4 = reinterpret_cast<const float4*>(h + (long)r * 64);
    const float4* hc4 = reinterpret_cast<const float4*>(h + (long)c * 64);

    #pragma unroll
    for (int half = 0; half < 2; half++) {
        const float4* src   = half ? hc4 : hr4;
        const float*  wbase = sWe1 + half * 64 * 64;
        for (int k4 = 0; k4 < 16; k4++) {
            const float4 x = src[k4];
            gemv_row(acc, pack2(x.x, x.x), wbase + (k4*4+0)*64);
            gemv_row(acc, pack2(x.y, x.y), wbase + (k4*4+1)*64);
            gemv_row(acc, pack2(x.z, x.z), wbase + (k4*4+2)*64);
            gemv_row(acc, pack2(x.w, x.w), wbase + (k4*4+3)*64);
        }
    }
    gemv_row(acc, pack2(radial, radial), sWe1 + 128 * 64);   // radial row (k=128)

    // ---- layer 2: ef = relu(be2 + relu(acc) @ We2) ----
    ull ef2[32];
    {
        const ulonglong2* b = reinterpret_cast<const ulonglong2*>(sbe2);
        #pragma unroll
        for (int j = 0; j < 16; j++) { ulonglong2 t = b[j]; ef2[2*j] = t.x; ef2[2*j+1] = t.y; }
    }
    for (int k2 = 0; k2 < 32; k2++) {
        const float2 a = unpack2(acc[k2]);
        const float x0 = fmaxf(a.x, 0.f), x1 = fmaxf(a.y, 0.f);
        gemv_row(ef2, pack2(x0, x0), sWe2 + (2*k2+0)*64);
        gemv_row(ef2, pack2(x1, x1), sWe2 + (2*k2+1)*64);
    }
    // unpack + relu into scalars (kept for gate input and scatter)
    float ef[64];
    #pragma unroll
    for (int j = 0; j < 32; j++) {
        const float2 a = unpack2(ef2[j]);
        ef[2*j]   = fmaxf(a.x, 0.f);
        ef[2*j+1] = fmaxf(a.y, 0.f);
    }

    // ---- gate: relu(ef @ Wc1 + bc1) @ Wc2 + bc2  (reuse acc as hidden) ----
    {
        const ulonglong2* b = reinterpret_cast<const ulonglong2*>(sbc1);
        #pragma unroll
        for (int j = 0; j < 16; j++) { ulonglong2 t = b[j]; acc[2*j] = t.x; acc[2*j+1] = t.y; }
    }
    for (int k2 = 0; k2 < 32; k2++) {
        gemv_row(acc, pack2(ef[2*k2],   ef[2*k2]),   sWc1 + (2*k2+0)*64);
        gemv_row(acc, pack2(ef[2*k2+1], ef[2*k2+1]), sWc1 + (2*k2+1)*64);
    }
    float gate = bc2[0];
    #pragma unroll
    for (int j = 0; j < 32; j++) {
        const float2 a = unpack2(acc[j]);
        gate += fmaxf(a.x, 0.f) * sWc2[2*j];
        gate += fmaxf(a.y, 0.f) * sWc2[2*j+1];
    }

    const float tx = fminf(fmaxf(cdx * gate, -100.f), 100.f);
    const float ty = fminf(fmaxf(cdy * gate, -100.f), 100.f);
    const float tz = fminf(fmaxf(cdz * gate, -100.f), 100.f);

    atomicAdd(&g_sum_t[r * 3 + 0], tx);
    atomicAdd(&g_sum_t[r * 3 + 1], ty);
    atomicAdd(&g_sum_t[r * 3 + 2], tz);
    atomicAdd(&g_cnt[r], 1.0f);

    float* dst = g_agg_h + (long)r * 64;
    #pragma unroll
    for (int j = 0; j < 16; j++)
        red_add_v4(dst + 4 * j, ef[4*j+0], ef[4*j+1], ef[4*j+2], ef[4*j+3]);
}

// ---------------- node kernel ----------------
// smem: sWn1 [128*64]=8192 @0, sbn1 [64] @8192, sWn2 [4096] @8256, sbn2 [64] @12352
//   -> 12416 floats = 49664 B
__global__ __launch_bounds__(128, 2)
void node_kernel(const float* __restrict__ h, const float* __restrict__ coord,
                 const float* __restrict__ vel,
                 const float* __restrict__ Wn1, const float* __restrict__ bn1,
                 const float* __restrict__ Wn2, const float* __restrict__ bn2,
                 float* __restrict__ out)
{
    extern __shared__ float s[];
    float* sWn1 = s;
    float* sbn1 = s + 8192;
    float* sWn2 = s + 8256;
    float* sbn2 = s + 12352;

    const int tid = threadIdx.x;
    for (int i = tid; i < 8192; i += 128) sWn1[i] = Wn1[i];
    for (int i = tid; i < 4096; i += 128) sWn2[i] = Wn2[i];
    if (tid < 64) { sbn1[tid] = bn1[tid]; sbn2[tid] = bn2[tid]; }
    __syncthreads();

    const int n = blockIdx.x * 128 + tid;
    if (n >= NN) return;

    ull acc[32];
    {
        const ulonglong2* b = reinterpret_cast<const ulonglong2*>(sbn1);
        #pragma unroll
        for (int j = 0; j < 16; j++) { ulonglong2 t = b[j]; acc[2*j] = t.x; acc[2*j+1] = t.y; }
    }

    const float4* hn = reinterpret_cast<const float4*>(h + (long)n * 64);
    const float4* an = reinterpret_cast<const float4*>(g_agg_h + (long)n * 64);

    #pragma unroll
    for (int half = 0; half < 2; half++) {
        const float4* src   = half ? an : hn;
        const float*  wbase = sWn1 + half * 64 * 64;
        for (int k4 = 0; k4 < 16; k4++) {
            const float4 x = src[k4];
            gemv_row(acc, pack2(x.x, x.x), wbase + (k4*4+0)*64);
            gemv_row(acc, pack2(x.y, x.y), wbase + (k4*4+1)*64);
            gemv_row(acc, pack2(x.z, x.z), wbase + (k4*4+2)*64);
            gemv_row(acc, pack2(x.w, x.w), wbase + (k4*4+3)*64);
        }
    }

    ull o2[32];
    {
        const ulonglong2* b = reinterpret_cast<const ulonglong2*>(sbn2);
        #pragma unroll
        for (int j = 0; j < 16; j++) { ulonglong2 t = b[j]; o2[2*j] = t.x; o2[2*j+1] = t.y; }
    }
    for (int k2 = 0; k2 < 32; k2++) {
        const float2 a = unpack2(acc[k2]);
        const float x0 = fmaxf(a.x, 0.f), x1 = fmaxf(a.y, 0.f);
        gemv_row(o2, pack2(x0, x0), sWn2 + (2*k2+0)*64);
        gemv_row(o2, pack2(x1, x1), sWn2 + (2*k2+1)*64);
    }

    // h_out = h + node_mlp(...)
    float4* outh = reinterpret_cast<float4*>(out + (long)n * 64);
    #pragma unroll
    for (int j = 0; j < 16; j++) {
        const float4 hv = hn[j];
        const float2 a = unpack2(o2[2*j]);
        const float2 bq = unpack2(o2[2*j+1]);
        float4 ov;
        ov.x = hv.x + a.x;  ov.y = hv.y + a.y;
        ov.z = hv.z + bq.x; ov.w = hv.w + bq.y;
        outh[j] = ov;
    }

    // coordinate / velocity update
    const float cnt = g_cnt[n];
    const float inv = cnt > 0.f ? 1.f / cnt : 0.f;
    const float ax = g_sum_t[n * 3 + 0] * inv;
    const float ay = g_sum_t[n * 3 + 1] * inv;
    const float az = g_sum_t[n * 3 + 2] * inv;
    const float invL = 0.125f;   // 1/N_LAYERS
    const float vx = vel[n * 3 + 0] + ax * invL;
    const float vy = vel[n * 3 + 1] + ay * invL;
    const float vz = vel[n * 3 + 2] + az * invL;
    const float cx = coord[n * 3 + 0] + vx * invL;
    const float cy = coord[n * 3 + 1] + vy * invL;
    const float cz = coord[n * 3 + 2] + vz * invL;

    float* outc = out + (long)NN * 64;
    float* outv = outc + (long)NN * 3;
    outc[n * 3 + 0] = cx; outc[n * 3 + 1] = cy; outc[n * 3 + 2] = cz;
    outv[n * 3 + 0] = vx; outv[n * 3 + 1] = vy; outv[n * 3 + 2] = vz;
}

// ---------------- launch ----------------
extern "C" void kernel_launch(void* const* d_in, const int* in_sizes, int n_in,
                              void* d_out, int out_size) {
    const float* h     = (const float*)d_in[0];
    const float* coord = (const float*)d_in[1];
    const float* vel   = (const float*)d_in[2];
    /* d_in[3] = vel_init (unused by reference) */
    const int*   ei    = (const int*)d_in[4];
    const float* We1 = (const float*)d_in[5];
    const float* be1 = (const float*)d_in[6];
    const float* We2 = (const float*)d_in[7];
    const float* be2 = (const float*)d_in[8];
    const float* Wn1 = (const float*)d_in[9];
    const float* bn1 = (const float*)d_in[10];
    const float* Wn2 = (const float*)d_in[11];
    const float* bn2 = (const float*)d_in[12];
    const float* Wc1 = (const float*)d_in[13];
    const float* bc1 = (const float*)d_in[14];
    const float* Wc2 = (const float*)d_in[15];
    const float* bc2 = (const float*)d_in[16];
    float* out = (float*)d_out;

    cudaFuncSetAttribute(edge_kernel, cudaFuncAttributeMaxDynamicSharedMemorySize, 66816);
    cudaFuncSetAttribute(node_kernel, cudaFuncAttributeMaxDynamicSharedMemorySize, 49664);

    zero_kernel<<<296, 256>>>();
    edge_kernel<<<NE / 128, 128, 66816>>>(h, coord, ei,
                                          We1, be1, We2, be2, Wc1, bc1, Wc2, bc2);
    node_kernel<<<(NN + 127) / 128, 128, 49664>>>(h, coord, vel,
                                                  Wn1, bn1, Wn2, bn2, out);
}